// round 15
// baseline (speedup 1.0000x reference)
#include <cuda_runtime.h>
#include <cuda_fp16.h>
#include <math.h>
#include <stdint.h>

#define Bn 8192
#define Dn 64
#define Cn 2048
#define EPSf 1e-6f
#define INV_SQRT_D 0.125f

// ---------------- global scratch ----------------
__device__ __half g_xh[Bn * 64];     // canonicalized x, fp16
__device__ __half g_ch[Cn * 64];     // codes, fp16
__device__ float g_c2[Cn];           // exact fp32 code norms
__device__ float4 g_cand[Bn * 8];    // per (row, nb): {d1,i1,d2,i2}
__device__ float g_loss;
__device__ unsigned int g_done;

// ---------------- helpers ----------------
__device__ __forceinline__ void gdc_wait() {
    asm volatile("griddepcontrol.wait;" ::: "memory");
}
__device__ __forceinline__ void gdc_launch() {
    asm volatile("griddepcontrol.launch_dependents;" ::: "memory");
}
__device__ __forceinline__ uint32_t smem_u32(const void* p) {
    uint32_t a;
    asm("{ .reg .u64 t; cvta.to.shared.u64 t, %1; cvt.u32.u64 %0, t; }"
        : "=r"(a) : "l"(p));
    return a;
}
__device__ __forceinline__ void ldmx4(uint32_t& r0, uint32_t& r1,
                                      uint32_t& r2, uint32_t& r3, uint32_t a) {
    asm volatile("ldmatrix.sync.aligned.m8n8.x4.shared.b16 {%0,%1,%2,%3}, [%4];"
                 : "=r"(r0), "=r"(r1), "=r"(r2), "=r"(r3) : "r"(a));
}
__device__ __forceinline__ void mma16816(float* c, const uint32_t* a,
                                         const uint32_t* b) {
    asm volatile(
        "mma.sync.aligned.m16n8k16.row.col.f32.f16.f16.f32 "
        "{%0,%1,%2,%3}, {%4,%5,%6,%7}, {%8,%9}, {%0,%1,%2,%3};"
        : "+f"(c[0]), "+f"(c[1]), "+f"(c[2]), "+f"(c[3])
        : "r"(a[0]), "r"(a[1]), "r"(a[2]), "r"(a[3]), "r"(b[0]), "r"(b[1]));
}

// ---------------- kernel 1: canon -> fp16 (2 rows/warp MLP) ---------------
// blocks [0, 512): x rows, 16/block. blocks [512, 640): code rows, 16/block.
#define XB (Bn / 16)
__global__ void canon_kernel(const float* __restrict__ x,
                             const float* __restrict__ pq,
                             const float* __restrict__ codes) {
    int lane = threadIdx.x & 31;
    int wid = threadIdx.x >> 5;
    if (blockIdx.x >= XB) {
        if (blockIdx.x == XB && threadIdx.x == 0) { g_loss = 0.0f; g_done = 0u; }
        int cbase = (blockIdx.x - XB) * 16 + wid * 2;
        float C0[2], C1[2], S[2];
#pragma unroll
        for (int r = 0; r < 2; ++r) {
            const float* cr = codes + (cbase + r) * Dn;
            C0[r] = cr[lane]; C1[r] = cr[lane + 32];
            S[r] = C0[r] * C0[r] + C1[r] * C1[r];
        }
#pragma unroll
        for (int o = 16; o; o >>= 1) {
            S[0] += __shfl_xor_sync(0xffffffffu, S[0], o);
            S[1] += __shfl_xor_sync(0xffffffffu, S[1], o);
        }
        if (lane < 2) g_c2[cbase + lane] = S[lane];
#pragma unroll
        for (int r = 0; r < 2; ++r) {
            __half* dst = &g_ch[(cbase + r) * 64];
            dst[lane] = __float2half(C0[r]);
            dst[lane + 32] = __float2half(C1[r]);
        }
        gdc_launch();
        return;
    }

    int rbase = blockIdx.x * 16 + wid * 2;
    float X0[2], X1[2], P0[2], P1[2];
#pragma unroll
    for (int r = 0; r < 2; ++r) {
        const float* xr = x + (rbase + r) * Dn;
        const float* pr = pq + (rbase + r) * Dn;
        X0[r] = xr[lane]; X1[r] = xr[lane + 32];
        P0[r] = pr[lane]; P1[r] = pr[lane + 32];
    }
    float v[8];
#pragma unroll
    for (int r = 0; r < 2; ++r) {
        v[r * 4 + 0] = P0[r] * P0[r] + P1[r] * P1[r];
        v[r * 4 + 1] = P0[r] + P1[r];
        v[r * 4 + 2] = X0[r] + X1[r];
        v[r * 4 + 3] = P0[r] * X0[r] + P1[r] * X1[r];
    }
#pragma unroll
    for (int o = 16; o; o >>= 1) {
#pragma unroll
        for (int k = 0; k < 8; ++k)
            v[k] += __shfl_xor_sync(0xffffffffu, v[k], o);
    }
#pragma unroll
    for (int r = 0; r < 2; ++r) {
        float inv = 1.0f / fmaxf(sqrtf(v[r * 4 + 0]), EPSf);
        float u0 = P0[r] * inv, u1 = P1[r] * inv;
        float s = INV_SQRT_D * v[r * 4 + 1] * inv;
        float p = INV_SQRT_D * v[r * 4 + 2];
        float q = v[r * 4 + 3] * inv;
        float dd = 1.0f + s + EPSf;
        float alpha = -p + (s * p - q) / dd;
        float beta  =  q - (p - s * q) / dd;
        float xc0 = X0[r] + alpha * u0 + beta * INV_SQRT_D;
        float xc1 = X1[r] + alpha * u1 + beta * INV_SQRT_D;
        __half* dst = &g_xh[(rbase + r) * 64];
        dst[lane] = __float2half(xc0);
        dst[lane + 32] = __float2half(xc1);
    }
    gdc_launch();
}

// ---------------- kernel 2: fp16 HMMA distance screen + top-2 -------------
// grid 1024 = 128 Mtiles(64 rows) x 8 Ntiles(256 codes); 256 threads,
// 8 warps (2 in M x 4 in N), warp tile 32x64, 2 CTAs per SM. (R10 config)
#define ROWB 144
#define ASZ (64 * ROWB)
#define BSZ (256 * ROWB)
#define SMEMSZ (ASZ + BSZ + 256 * 4)

__global__ void __launch_bounds__(256, 2) argmin_kernel(void) {
    extern __shared__ char sm[];
    char* Asm = sm;
    char* Bsm = sm + ASZ;
    float* c2s = (float*)(sm + ASZ + BSZ);
    uint32_t* epi = (uint32_t*)Bsm;        // aliased onto B after mainloop

    const int tid = threadIdx.x;
    const int lane = tid & 31;
    const int wid = tid >> 5;
    const int wm = wid & 1;
    const int wn = wid >> 1;
    const int mb = blockIdx.x >> 3;
    const int nb = blockIdx.x & 7;

    const uint32_t smbA = smem_u32(Asm);
    const uint32_t smbB = smem_u32(Bsm);

    gdc_wait();

    // stage A: 64 rows x 64 fp16
#pragma unroll 2
    for (int i = tid; i < 64 * 8; i += 256) {
        int r = i >> 3, f4 = i & 7;
        uint4 v = *reinterpret_cast<const uint4*>(
            &g_xh[(mb * 64 + r) * 64 + f4 * 8]);
        *reinterpret_cast<uint4*>(Asm + r * ROWB + f4 * 16) = v;
    }
    // stage B: 256 code rows x 64 fp16
#pragma unroll 4
    for (int i = tid; i < 256 * 8; i += 256) {
        int r = i >> 3, f4 = i & 7;
        uint4 v = *reinterpret_cast<const uint4*>(
            &g_ch[(nb * 256 + r) * 64 + f4 * 8]);
        *reinterpret_cast<uint4*>(Bsm + r * ROWB + f4 * 16) = v;
    }
    if (tid < 256) c2s[tid] = g_c2[nb * 256 + tid];
    __syncthreads();

    float acc[2][8][4];
#pragma unroll
    for (int i = 0; i < 2; i++)
#pragma unroll
        for (int j = 0; j < 8; j++)
#pragma unroll
            for (int kk = 0; kk < 4; kk++) acc[i][j][kk] = 0.0f;

#pragma unroll
    for (int ks = 0; ks < 4; ++ks) {
        const int kb = ks * 32;
        uint32_t a[2][4];
#pragma unroll
        for (int mi = 0; mi < 2; ++mi) {
            uint32_t addr = smbA + (wm * 32 + mi * 16 + (lane & 15)) * ROWB
                          + kb + ((lane >> 4) * 16);
            ldmx4(a[mi][0], a[mi][1], a[mi][2], a[mi][3], addr);
        }
        uint32_t b[8][2];
#pragma unroll
        for (int nj = 0; nj < 4; ++nj) {
            int nrow = wn * 64 + nj * 16 + (((lane >> 4) & 1) * 8) + (lane & 7);
            uint32_t addr = smbB + nrow * ROWB + kb + (((lane >> 3) & 1) * 16);
            ldmx4(b[nj * 2][0], b[nj * 2][1],
                  b[nj * 2 + 1][0], b[nj * 2 + 1][1], addr);
        }
#pragma unroll
        for (int mi = 0; mi < 2; ++mi)
#pragma unroll
            for (int nj = 0; nj < 8; ++nj)
                mma16816(acc[mi][nj], a[mi], b[nj]);
    }

    __syncthreads();   // done reading B; epi aliases B

    // warp-level top-2 per row over this warp's 64 cols
#pragma unroll
    for (int mi = 0; mi < 2; ++mi) {
#pragma unroll
        for (int h = 0; h < 2; ++h) {
            float d1 = INFINITY, d2 = INFINITY;
            int i1 = 0, i2 = 0;
#pragma unroll
            for (int nj = 0; nj < 8; ++nj) {
#pragma unroll
                for (int s = 0; s < 2; ++s) {
                    int cloc = wn * 64 + nj * 8 + 2 * (lane & 3) + s;
                    float d = fmaf(-2.0f, acc[mi][nj][h * 2 + s], c2s[cloc]);
                    int gi = nb * 256 + cloc;
                    if (d < d1) { d2 = d1; i2 = i1; d1 = d; i1 = gi; }
                    else if (d < d2) { d2 = d; i2 = gi; }
                }
            }
#pragma unroll
            for (int off = 1; off <= 2; off <<= 1) {
                float od1 = __shfl_xor_sync(0xffffffffu, d1, off);
                int   oi1 = __shfl_xor_sync(0xffffffffu, i1, off);
                float od2 = __shfl_xor_sync(0xffffffffu, d2, off);
                int   oi2 = __shfl_xor_sync(0xffffffffu, i2, off);
                if (d1 <= od1) {
                    if (od1 < d2) { d2 = od1; i2 = oi1; }
                } else {
                    if (d1 <= od2) { d2 = d1; i2 = i1; }
                    else           { d2 = od2; i2 = oi2; }
                    d1 = od1; i1 = oi1;
                }
            }
            if ((lane & 3) == 0) {
                int rowL = wm * 32 + mi * 16 + (lane >> 2) + h * 8;
                uint32_t* e = epi + (rowL * 4 + wn) * 4;
                e[0] = __float_as_uint(d1); e[1] = (uint32_t)i1;
                e[2] = __float_as_uint(d2); e[3] = (uint32_t)i2;
            }
        }
    }
    __syncthreads();

    // merge 4 n-warps -> block top-2 per row
    if (tid < 64) {
        float d1 = INFINITY, d2 = INFINITY;
        int i1 = 0, i2 = 0;
#pragma unroll
        for (int w = 0; w < 4; ++w) {
            const uint32_t* e = epi + (tid * 4 + w) * 4;
            float a1 = __uint_as_float(e[0]); int b1i = (int)e[1];
            float a2 = __uint_as_float(e[2]); int b2i = (int)e[3];
            if (a1 < d1) { d2 = d1; i2 = i1; d1 = a1; i1 = b1i; }
            else if (a1 < d2) { d2 = a1; i2 = b1i; }
            if (a2 < d1) { d2 = d1; i2 = i1; d1 = a2; i1 = b2i; }
            else if (a2 < d2) { d2 = a2; i2 = b2i; }
        }
        int rowG = mb * 64 + tid;
        g_cand[rowG * 8 + nb] =
            make_float4(d1, __int_as_float(i1), d2, __int_as_float(i2));
    }
    gdc_launch();
}

// ---------------- kernel 3: prune 16->4, exact rescore, rotate, loss ------
__global__ void final_kernel(const float* __restrict__ x,
                             const float* __restrict__ pq,
                             const float* __restrict__ codes,
                             float* __restrict__ out,
                             int has_idx, int has_loss) {
    __shared__ float bl;
    int tid = threadIdx.x;
    if (tid == 0) bl = 0.0f;
    __syncthreads();

    int row = blockIdx.x * 8 + (tid >> 5);
    int lane = tid & 31;

    gdc_wait();

    // prune: top-4 by screened distance among 16 stored candidates
    float td[4] = {INFINITY, INFINITY, INFINITY, INFINITY};
    int   ti[4] = {0, 0, 0, 0};
#pragma unroll
    for (int nb = 0; nb < 8; ++nb) {
        float4 cd = g_cand[row * 8 + nb];
#pragma unroll
        for (int h = 0; h < 2; ++h) {
            float d = h ? cd.z : cd.x;
            int   ix = __float_as_int(h ? cd.w : cd.y);
#pragma unroll
            for (int k = 0; k < 4; ++k) {
                if (d < td[k] || (d == td[k] && ix < ti[k])) {
                    float pd = td[k]; int pi = ti[k];
                    td[k] = d; ti[k] = ix; d = pd; ix = pi;
                }
            }
        }
    }

    // chain 1: canon reductions + |x|^2
    const float* pr = pq + row * Dn;
    float p0 = pr[lane], p1 = pr[lane + 32];
    const float* xr = x + row * Dn;
    float x0 = xr[lane], x1 = xr[lane + 32];

    float n2 = p0 * p0 + p1 * p1;
    float sp = p0 + p1;
    float sx = x0 + x1;
    float px = p0 * x0 + p1 * x1;
    float x2 = x0 * x0 + x1 * x1;
#pragma unroll
    for (int o = 16; o; o >>= 1) {
        n2 += __shfl_xor_sync(0xffffffffu, n2, o);
        sp += __shfl_xor_sync(0xffffffffu, sp, o);
        sx += __shfl_xor_sync(0xffffffffu, sx, o);
        px += __shfl_xor_sync(0xffffffffu, px, o);
        x2 += __shfl_xor_sync(0xffffffffu, x2, o);
    }
    float inv = 1.0f / fmaxf(sqrtf(n2), EPSf);
    float u0 = p0 * inv, u1 = p1 * inv;
    float s  = INV_SQRT_D * sp * inv;
    float dd = 1.0f + s + EPSf;
    float xc0, xc1;
    {
        float p = INV_SQRT_D * sx;
        float q = px * inv;
        float alpha = -p + (s * p - q) / dd;
        float beta  =  q - (p - s * q) / dd;
        xc0 = x0 + alpha * u0 + beta * INV_SQRT_D;
        xc1 = x1 + alpha * u1 + beta * INV_SQRT_D;
    }

    // chain 2: per-candidate partials {xc.c, sum(c), p.c, x.c} (16 values)
    float c0k[4], c1k[4];
    float dk[4], sc[4], pc[4], xq[4];
#pragma unroll
    for (int k = 0; k < 4; ++k) {
        const float* cr = codes + ti[k] * Dn;
        c0k[k] = cr[lane]; c1k[k] = cr[lane + 32];
        dk[k] = xc0 * c0k[k] + xc1 * c1k[k];
        sc[k] = c0k[k] + c1k[k];
        pc[k] = p0 * c0k[k] + p1 * c1k[k];
        xq[k] = x0 * c0k[k] + x1 * c1k[k];
    }
#pragma unroll
    for (int o = 16; o; o >>= 1) {
#pragma unroll
        for (int k = 0; k < 4; ++k) {
            dk[k] += __shfl_xor_sync(0xffffffffu, dk[k], o);
            sc[k] += __shfl_xor_sync(0xffffffffu, sc[k], o);
            pc[k] += __shfl_xor_sync(0xffffffffu, pc[k], o);
            xq[k] += __shfl_xor_sync(0xffffffffu, xq[k], o);
        }
    }

    // select winner (same dk rounding as previous passing kernels)
    int sel = 0;
    float bd = g_c2[ti[0]] - 2.0f * dk[0];
#pragma unroll
    for (int k = 1; k < 4; ++k) {
        float d = g_c2[ti[k]] - 2.0f * dk[k];
        if (d < bd || (d == bd && ti[k] < ti[sel])) { bd = d; sel = k; }
    }
    int idx = ti[sel];

    // scalar epilogue: everything from chain-2 partials
    float qc0 = c0k[sel], qc1 = c1k[sel];
#pragma unroll
    for (int k = 0; k < 4; ++k) {
        if (k == sel) { qc0 = c0k[k]; qc1 = c1k[k]; }
    }
    float pp = INV_SQRT_D * sc[sel];
    float qq = pc[sel] * inv;
    float a = pp + (s * pp - qq) / dd;
    float b = -qq + (s * qq - pp) / dd;

    out[row * Dn + lane]      = qc0 + a * u0 + b * INV_SQRT_D;
    out[row * Dn + lane + 32] = qc1 + a * u1 + b * INV_SQRT_D;

    if (lane == 0) {
        float l = x2 - 2.0f * xq[sel] + g_c2[idx];
        if (has_idx) out[Bn * Dn + row] = (float)idx;
        atomicAdd(&bl, l);
    }
    __syncthreads();
    if (tid == 0) {
        atomicAdd(&g_loss, bl);
        __threadfence();
        unsigned int n = atomicAdd(&g_done, 1u);
        if (n == gridDim.x - 1) {
            if (has_loss) out[Bn * Dn + Bn] = g_loss * (1.25f / (float)Bn);
        }
    }
}

// ---------------- launcher ----------------
extern "C" void kernel_launch(void* const* d_in, const int* in_sizes, int n_in,
                              void* d_out, int out_size) {
    const float* x     = (const float*)d_in[0];
    const float* pq    = (const float*)d_in[1];
    const float* codes = (const float*)d_in[2];
    float* out = (float*)d_out;

    int has_idx  = out_size >= Bn * Dn + Bn;
    int has_loss = out_size >= Bn * Dn + Bn + 1;

    cudaFuncSetAttribute(argmin_kernel,
                         cudaFuncAttributeMaxDynamicSharedMemorySize, SMEMSZ);

    canon_kernel<<<XB + Cn / 16, 256>>>(x, pq, codes);

    cudaLaunchAttribute attr[1];
    attr[0].id = cudaLaunchAttributeProgrammaticStreamSerialization;
    attr[0].val.programmaticStreamSerializationAllowed = 1;

    {
        cudaLaunchConfig_t cfg = {};
        cfg.gridDim = dim3((Bn / 64) * 8);
        cfg.blockDim = dim3(256);
        cfg.dynamicSmemBytes = SMEMSZ;
        cfg.stream = 0;
        cfg.attrs = attr;
        cfg.numAttrs = 1;
        cudaLaunchKernelEx(&cfg, argmin_kernel);
    }
    {
        cudaLaunchConfig_t cfg = {};
        cfg.gridDim = dim3(Bn / 8);
        cfg.blockDim = dim3(256);
        cfg.dynamicSmemBytes = 0;
        cfg.stream = 0;
        cfg.attrs = attr;
        cfg.numAttrs = 1;
        cudaLaunchKernelEx(&cfg, final_kernel, x, pq, codes, out,
                           has_idx, has_loss);
    }
}

// round 16
// speedup vs baseline: 1.1232x; 1.1232x over previous
#include <cuda_runtime.h>
#include <cuda_fp16.h>
#include <math.h>
#include <stdint.h>

#define Bn 8192
#define Dn 64
#define Cn 2048
#define EPSf 1e-6f
#define INV_SQRT_D 0.125f

// ---------------- global scratch ----------------
__device__ __half g_xh[Bn * 64];     // canonicalized x, fp16
__device__ __half g_ch[Cn * 64];     // codes, fp16
__device__ float g_c2[Cn];           // exact fp32 code norms
__device__ float4 g_cand[Bn * 8];    // per (row, nb): {d1,i1,d2,i2}
__device__ float g_loss;
__device__ unsigned int g_done;

// ---------------- helpers ----------------
__device__ __forceinline__ void gdc_wait() {
    asm volatile("griddepcontrol.wait;" ::: "memory");
}
__device__ __forceinline__ void gdc_launch() {
    asm volatile("griddepcontrol.launch_dependents;" ::: "memory");
}
__device__ __forceinline__ uint32_t smem_u32(const void* p) {
    uint32_t a;
    asm("{ .reg .u64 t; cvta.to.shared.u64 t, %1; cvt.u32.u64 %0, t; }"
        : "=r"(a) : "l"(p));
    return a;
}
__device__ __forceinline__ void ldmx4(uint32_t& r0, uint32_t& r1,
                                      uint32_t& r2, uint32_t& r3, uint32_t a) {
    asm volatile("ldmatrix.sync.aligned.m8n8.x4.shared.b16 {%0,%1,%2,%3}, [%4];"
                 : "=r"(r0), "=r"(r1), "=r"(r2), "=r"(r3) : "r"(a));
}
__device__ __forceinline__ void mma16816(float* c, const uint32_t* a,
                                         const uint32_t* b) {
    asm volatile(
        "mma.sync.aligned.m16n8k16.row.col.f32.f16.f16.f32 "
        "{%0,%1,%2,%3}, {%4,%5,%6,%7}, {%8,%9}, {%0,%1,%2,%3};"
        : "+f"(c[0]), "+f"(c[1]), "+f"(c[2]), "+f"(c[3])
        : "r"(a[0]), "r"(a[1]), "r"(a[2]), "r"(a[3]), "r"(b[0]), "r"(b[1]));
}

// ---------------- kernel 1: canon -> fp16, codes -> fp16 + norms ----------
// blocks [0, Bn/8): one warp per x row.
// blocks [Bn/8, Bn/8 + Cn/8): one warp per code row.
__global__ void canon_kernel(const float* __restrict__ x,
                             const float* __restrict__ pq,
                             const float* __restrict__ codes) {
    int lane = threadIdx.x & 31;
    if (blockIdx.x >= Bn / 8) {
        int c = (blockIdx.x - Bn / 8) * 8 + (threadIdx.x >> 5);
        if (blockIdx.x == Bn / 8 && threadIdx.x == 0) { g_loss = 0.0f; g_done = 0u; }
        const float* cr = codes + c * Dn;
        float c0 = cr[lane], c1 = cr[lane + 32];
        float s = c0 * c0 + c1 * c1;
#pragma unroll
        for (int o = 16; o; o >>= 1) s += __shfl_xor_sync(0xffffffffu, s, o);
        if (lane == 0) g_c2[c] = s;
        __half* dst = &g_ch[c * 64];
        dst[lane] = __float2half(c0);
        dst[lane + 32] = __float2half(c1);
        gdc_launch();
        return;
    }

    int row = blockIdx.x * 8 + (threadIdx.x >> 5);
    const float* xr = x + row * Dn;
    const float* pr = pq + row * Dn;
    float x0 = xr[lane], x1 = xr[lane + 32];
    float p0 = pr[lane], p1 = pr[lane + 32];

    float n2 = p0 * p0 + p1 * p1;
    float sp = p0 + p1;
    float sx = x0 + x1;
    float px = p0 * x0 + p1 * x1;
#pragma unroll
    for (int o = 16; o; o >>= 1) {
        n2 += __shfl_xor_sync(0xffffffffu, n2, o);
        sp += __shfl_xor_sync(0xffffffffu, sp, o);
        sx += __shfl_xor_sync(0xffffffffu, sx, o);
        px += __shfl_xor_sync(0xffffffffu, px, o);
    }
    float inv = 1.0f / fmaxf(sqrtf(n2), EPSf);
    float u0 = p0 * inv, u1 = p1 * inv;
    float s = INV_SQRT_D * sp * inv;
    float p = INV_SQRT_D * sx;
    float q = px * inv;
    float dd = 1.0f + s + EPSf;
    float alpha = -p + (s * p - q) / dd;
    float beta  =  q - (p - s * q) / dd;
    float xc0 = x0 + alpha * u0 + beta * INV_SQRT_D;
    float xc1 = x1 + alpha * u1 + beta * INV_SQRT_D;

    __half* dst = &g_xh[row * 64];
    dst[lane] = __float2half(xc0);
    dst[lane + 32] = __float2half(xc1);
    gdc_launch();
}

// ---------------- kernel 2: fp16 HMMA distance screen + top-2 -------------
// grid 1024 = 128 Mtiles(64 rows) x 8 Ntiles(256 codes); 256 threads,
// 8 warps (2 in M x 4 in N), warp tile 32x64, 2 CTAs per SM. (R10 config)
#define ROWB 144
#define ASZ (64 * ROWB)
#define BSZ (256 * ROWB)
#define SMEMSZ (ASZ + BSZ + 256 * 4)

__global__ void __launch_bounds__(256, 2) argmin_kernel(void) {
    extern __shared__ char sm[];
    char* Asm = sm;
    char* Bsm = sm + ASZ;
    float* c2s = (float*)(sm + ASZ + BSZ);
    uint32_t* epi = (uint32_t*)Bsm;        // aliased onto B after mainloop

    const int tid = threadIdx.x;
    const int lane = tid & 31;
    const int wid = tid >> 5;
    const int wm = wid & 1;
    const int wn = wid >> 1;
    const int mb = blockIdx.x >> 3;
    const int nb = blockIdx.x & 7;

    const uint32_t smbA = smem_u32(Asm);
    const uint32_t smbB = smem_u32(Bsm);

    gdc_wait();   // wait for canon's g_xh/g_ch/g_c2 before consuming

    // stage A: 64 rows x 64 fp16
#pragma unroll 2
    for (int i = tid; i < 64 * 8; i += 256) {
        int r = i >> 3, f4 = i & 7;
        uint4 v = *reinterpret_cast<const uint4*>(
            &g_xh[(mb * 64 + r) * 64 + f4 * 8]);
        *reinterpret_cast<uint4*>(Asm + r * ROWB + f4 * 16) = v;
    }
    // stage B: 256 code rows x 64 fp16
#pragma unroll 4
    for (int i = tid; i < 256 * 8; i += 256) {
        int r = i >> 3, f4 = i & 7;
        uint4 v = *reinterpret_cast<const uint4*>(
            &g_ch[(nb * 256 + r) * 64 + f4 * 8]);
        *reinterpret_cast<uint4*>(Bsm + r * ROWB + f4 * 16) = v;
    }
    if (tid < 256) c2s[tid] = g_c2[nb * 256 + tid];
    __syncthreads();

    float acc[2][8][4];
#pragma unroll
    for (int i = 0; i < 2; i++)
#pragma unroll
        for (int j = 0; j < 8; j++)
#pragma unroll
            for (int kk = 0; kk < 4; kk++) acc[i][j][kk] = 0.0f;

#pragma unroll
    for (int ks = 0; ks < 4; ++ks) {
        const int kb = ks * 32;
        uint32_t a[2][4];
#pragma unroll
        for (int mi = 0; mi < 2; ++mi) {
            uint32_t addr = smbA + (wm * 32 + mi * 16 + (lane & 15)) * ROWB
                          + kb + ((lane >> 4) * 16);
            ldmx4(a[mi][0], a[mi][1], a[mi][2], a[mi][3], addr);
        }
        uint32_t b[8][2];
#pragma unroll
        for (int nj = 0; nj < 4; ++nj) {
            int nrow = wn * 64 + nj * 16 + (((lane >> 4) & 1) * 8) + (lane & 7);
            uint32_t addr = smbB + nrow * ROWB + kb + (((lane >> 3) & 1) * 16);
            ldmx4(b[nj * 2][0], b[nj * 2][1],
                  b[nj * 2 + 1][0], b[nj * 2 + 1][1], addr);
        }
#pragma unroll
        for (int mi = 0; mi < 2; ++mi)
#pragma unroll
            for (int nj = 0; nj < 8; ++nj)
                mma16816(acc[mi][nj], a[mi], b[nj]);
    }

    __syncthreads();   // done reading B; epi aliases B

    // warp-level top-2 per row over this warp's 64 cols
#pragma unroll
    for (int mi = 0; mi < 2; ++mi) {
#pragma unroll
        for (int h = 0; h < 2; ++h) {
            float d1 = INFINITY, d2 = INFINITY;
            int i1 = 0, i2 = 0;
#pragma unroll
            for (int nj = 0; nj < 8; ++nj) {
#pragma unroll
                for (int s = 0; s < 2; ++s) {
                    int cloc = wn * 64 + nj * 8 + 2 * (lane & 3) + s;
                    float d = fmaf(-2.0f, acc[mi][nj][h * 2 + s], c2s[cloc]);
                    int gi = nb * 256 + cloc;
                    if (d < d1) { d2 = d1; i2 = i1; d1 = d; i1 = gi; }
                    else if (d < d2) { d2 = d; i2 = gi; }
                }
            }
#pragma unroll
            for (int off = 1; off <= 2; off <<= 1) {
                float od1 = __shfl_xor_sync(0xffffffffu, d1, off);
                int   oi1 = __shfl_xor_sync(0xffffffffu, i1, off);
                float od2 = __shfl_xor_sync(0xffffffffu, d2, off);
                int   oi2 = __shfl_xor_sync(0xffffffffu, i2, off);
                if (d1 <= od1) {
                    if (od1 < d2) { d2 = od1; i2 = oi1; }
                } else {
                    if (d1 <= od2) { d2 = d1; i2 = i1; }
                    else           { d2 = od2; i2 = oi2; }
                    d1 = od1; i1 = oi1;
                }
            }
            if ((lane & 3) == 0) {
                int rowL = wm * 32 + mi * 16 + (lane >> 2) + h * 8;
                uint32_t* e = epi + (rowL * 4 + wn) * 4;
                e[0] = __float_as_uint(d1); e[1] = (uint32_t)i1;
                e[2] = __float_as_uint(d2); e[3] = (uint32_t)i2;
            }
        }
    }
    __syncthreads();

    // merge 4 n-warps -> block top-2 per row
    if (tid < 64) {
        float d1 = INFINITY, d2 = INFINITY;
        int i1 = 0, i2 = 0;
#pragma unroll
        for (int w = 0; w < 4; ++w) {
            const uint32_t* e = epi + (tid * 4 + w) * 4;
            float a1 = __uint_as_float(e[0]); int b1i = (int)e[1];
            float a2 = __uint_as_float(e[2]); int b2i = (int)e[3];
            if (a1 < d1) { d2 = d1; i2 = i1; d1 = a1; i1 = b1i; }
            else if (a1 < d2) { d2 = a1; i2 = b1i; }
            if (a2 < d1) { d2 = d1; i2 = i1; d1 = a2; i1 = b2i; }
            else if (a2 < d2) { d2 = a2; i2 = b2i; }
        }
        int rowG = mb * 64 + tid;
        g_cand[rowG * 8 + nb] =
            make_float4(d1, __int_as_float(i1), d2, __int_as_float(i2));
    }
    gdc_launch();
}

// ---------------- kernel 3: prune 16->4, exact rescore, rotate, loss ------
__global__ void final_kernel(const float* __restrict__ x,
                             const float* __restrict__ pq,
                             const float* __restrict__ codes,
                             float* __restrict__ out,
                             int has_idx, int has_loss) {
    __shared__ float bl;
    int tid = threadIdx.x;
    if (tid == 0) bl = 0.0f;
    __syncthreads();

    int row = blockIdx.x * 8 + (tid >> 5);
    int lane = tid & 31;

    gdc_wait();   // wait for argmin's g_cand before consuming

    // prune: top-4 by screened distance among 16 stored candidates
    float td[4] = {INFINITY, INFINITY, INFINITY, INFINITY};
    int   ti[4] = {0, 0, 0, 0};
#pragma unroll
    for (int nb = 0; nb < 8; ++nb) {
        float4 cd = g_cand[row * 8 + nb];
#pragma unroll
        for (int h = 0; h < 2; ++h) {
            float d = h ? cd.z : cd.x;
            int   ix = __float_as_int(h ? cd.w : cd.y);
#pragma unroll
            for (int k = 0; k < 4; ++k) {
                if (d < td[k] || (d == td[k] && ix < ti[k])) {
                    float pd = td[k]; int pi = ti[k];
                    td[k] = d; ti[k] = ix; d = pd; ix = pi;
                }
            }
        }
    }

    // recompute x_canonical
    const float* pr = pq + row * Dn;
    float p0 = pr[lane], p1 = pr[lane + 32];
    const float* xr = x + row * Dn;
    float x0 = xr[lane], x1 = xr[lane + 32];

    float n2 = p0 * p0 + p1 * p1;
    float sp = p0 + p1;
    float sx = x0 + x1;
    float px = p0 * x0 + p1 * x1;
#pragma unroll
    for (int o = 16; o; o >>= 1) {
        n2 += __shfl_xor_sync(0xffffffffu, n2, o);
        sp += __shfl_xor_sync(0xffffffffu, sp, o);
        sx += __shfl_xor_sync(0xffffffffu, sx, o);
        px += __shfl_xor_sync(0xffffffffu, px, o);
    }
    float inv = 1.0f / fmaxf(sqrtf(n2), EPSf);
    float u0 = p0 * inv, u1 = p1 * inv;
    float s  = INV_SQRT_D * sp * inv;
    float xc0, xc1;
    {
        float p = INV_SQRT_D * sx;
        float q = px * inv;
        float dd = 1.0f + s + EPSf;
        float alpha = -p + (s * p - q) / dd;
        float beta  =  q - (p - s * q) / dd;
        xc0 = x0 + alpha * u0 + beta * INV_SQRT_D;
        xc1 = x1 + alpha * u1 + beta * INV_SQRT_D;
    }

    // exact fp32 rescore of the 4 pruned candidates (|c|^2 exact from g_c2)
    float dk[4];
#pragma unroll
    for (int k = 0; k < 4; ++k) {
        const float* cr = codes + ti[k] * Dn;
        dk[k] = xc0 * cr[lane] + xc1 * cr[lane + 32];
    }
#pragma unroll
    for (int o = 16; o; o >>= 1) {
#pragma unroll
        for (int k = 0; k < 4; ++k)
            dk[k] += __shfl_xor_sync(0xffffffffu, dk[k], o);
    }
    int best = ti[0];
    float bd = g_c2[ti[0]] - 2.0f * dk[0];
#pragma unroll
    for (int k = 1; k < 4; ++k) {
        float d = g_c2[ti[k]] - 2.0f * dk[k];
        if (d < bd || (d == bd && ti[k] < best)) { bd = d; best = ti[k]; }
    }
    int idx = best;

    // rotate chosen code back, write outputs, accumulate loss
    const float* qcr = codes + idx * Dn;
    float qc0 = qcr[lane], qc1 = qcr[lane + 32];

    float sq = qc0 + qc1;
    float pqv = u0 * qc0 + u1 * qc1;
    float l = (x0 - qc0) * (x0 - qc0) + (x1 - qc1) * (x1 - qc1);
#pragma unroll
    for (int o = 16; o; o >>= 1) {
        sq  += __shfl_xor_sync(0xffffffffu, sq, o);
        pqv += __shfl_xor_sync(0xffffffffu, pqv, o);
        l   += __shfl_xor_sync(0xffffffffu, l, o);
    }
    float pp = INV_SQRT_D * sq;
    float qq = pqv;
    float dd = 1.0f + s + EPSf;
    float a = pp + (s * pp - qq) / dd;
    float b = -qq + (s * qq - pp) / dd;

    out[row * Dn + lane]      = qc0 + a * u0 + b * INV_SQRT_D;
    out[row * Dn + lane + 32] = qc1 + a * u1 + b * INV_SQRT_D;

    if (lane == 0) {
        if (has_idx) out[Bn * Dn + row] = (float)idx;
        atomicAdd(&bl, l);
    }
    __syncthreads();
    if (tid == 0) {
        atomicAdd(&g_loss, bl);
        __threadfence();
        unsigned int n = atomicAdd(&g_done, 1u);
        if (n == gridDim.x - 1) {
            if (has_loss) out[Bn * Dn + Bn] = g_loss * (1.25f / (float)Bn);
        }
    }
}

// ---------------- launcher ----------------
extern "C" void kernel_launch(void* const* d_in, const int* in_sizes, int n_in,
                              void* d_out, int out_size) {
    const float* x     = (const float*)d_in[0];
    const float* pq    = (const float*)d_in[1];
    const float* codes = (const float*)d_in[2];
    float* out = (float*)d_out;

    int has_idx  = out_size >= Bn * Dn + Bn;
    int has_loss = out_size >= Bn * Dn + Bn + 1;

    cudaFuncSetAttribute(argmin_kernel,
                         cudaFuncAttributeMaxDynamicSharedMemorySize, SMEMSZ);

    canon_kernel<<<Bn / 8 + Cn / 8, 256>>>(x, pq, codes);

    cudaLaunchAttribute attr[1];
    attr[0].id = cudaLaunchAttributeProgrammaticStreamSerialization;
    attr[0].val.programmaticStreamSerializationAllowed = 1;

    {
        cudaLaunchConfig_t cfg = {};
        cfg.gridDim = dim3((Bn / 64) * 8);
        cfg.blockDim = dim3(256);
        cfg.dynamicSmemBytes = SMEMSZ;
        cfg.stream = 0;
        cfg.attrs = attr;
        cfg.numAttrs = 1;
        cudaLaunchKernelEx(&cfg, argmin_kernel);
    }
    {
        cudaLaunchConfig_t cfg = {};
        cfg.gridDim = dim3(Bn / 8);
        cfg.blockDim = dim3(256);
        cfg.dynamicSmemBytes = 0;
        cfg.stream = 0;
        cfg.attrs = attr;
        cfg.numAttrs = 1;
        cudaLaunchKernelEx(&cfg, final_kernel, x, pq, codes, out,
                           has_idx, has_loss);
    }
}

// round 17
// speedup vs baseline: 1.1939x; 1.0629x over previous
#include <cuda_runtime.h>
#include <cuda_fp16.h>
#include <math.h>
#include <stdint.h>

#define Bn 8192
#define Dn 64
#define Cn 2048
#define EPSf 1e-6f
#define INV_SQRT_D 0.125f

// ---------------- global scratch ----------------
__device__ __half g_xh[Bn * 64];     // canonicalized x, fp16
__device__ float g_xc[Bn * 64];      // canonicalized x, fp32 (for final)
__device__ float2 g_ri[Bn];          // per-row {inv, s}
__device__ __half g_ch[Cn * 64];     // codes, fp16
__device__ float g_c2[Cn];           // exact fp32 code norms
__device__ float4 g_cand[Bn * 8];    // per (row, nb): {d1,i1,d2,i2}
__device__ float g_loss;
__device__ unsigned int g_done;

// ---------------- helpers ----------------
__device__ __forceinline__ void gdc_wait() {
    asm volatile("griddepcontrol.wait;" ::: "memory");
}
__device__ __forceinline__ void gdc_launch() {
    asm volatile("griddepcontrol.launch_dependents;" ::: "memory");
}
__device__ __forceinline__ uint32_t smem_u32(const void* p) {
    uint32_t a;
    asm("{ .reg .u64 t; cvta.to.shared.u64 t, %1; cvt.u32.u64 %0, t; }"
        : "=r"(a) : "l"(p));
    return a;
}
__device__ __forceinline__ void ldmx4(uint32_t& r0, uint32_t& r1,
                                      uint32_t& r2, uint32_t& r3, uint32_t a) {
    asm volatile("ldmatrix.sync.aligned.m8n8.x4.shared.b16 {%0,%1,%2,%3}, [%4];"
                 : "=r"(r0), "=r"(r1), "=r"(r2), "=r"(r3) : "r"(a));
}
__device__ __forceinline__ void mma16816(float* c, const uint32_t* a,
                                         const uint32_t* b) {
    asm volatile(
        "mma.sync.aligned.m16n8k16.row.col.f32.f16.f16.f32 "
        "{%0,%1,%2,%3}, {%4,%5,%6,%7}, {%8,%9}, {%0,%1,%2,%3};"
        : "+f"(c[0]), "+f"(c[1]), "+f"(c[2]), "+f"(c[3])
        : "r"(a[0]), "r"(a[1]), "r"(a[2]), "r"(a[3]), "r"(b[0]), "r"(b[1]));
}

// ---------------- kernel 1: canon -> fp16 + fp32 + params, codes ----------
// blocks [0, Bn/8): one warp per x row.
// blocks [Bn/8, Bn/8 + Cn/8): one warp per code row.
__global__ void canon_kernel(const float* __restrict__ x,
                             const float* __restrict__ pq,
                             const float* __restrict__ codes) {
    int lane = threadIdx.x & 31;
    if (blockIdx.x >= Bn / 8) {
        int c = (blockIdx.x - Bn / 8) * 8 + (threadIdx.x >> 5);
        if (blockIdx.x == Bn / 8 && threadIdx.x == 0) { g_loss = 0.0f; g_done = 0u; }
        const float* cr = codes + c * Dn;
        float c0 = cr[lane], c1 = cr[lane + 32];
        float s = c0 * c0 + c1 * c1;
#pragma unroll
        for (int o = 16; o; o >>= 1) s += __shfl_xor_sync(0xffffffffu, s, o);
        if (lane == 0) g_c2[c] = s;
        __half* dst = &g_ch[c * 64];
        dst[lane] = __float2half(c0);
        dst[lane + 32] = __float2half(c1);
        gdc_launch();
        return;
    }

    int row = blockIdx.x * 8 + (threadIdx.x >> 5);
    const float* xr = x + row * Dn;
    const float* pr = pq + row * Dn;
    float x0 = xr[lane], x1 = xr[lane + 32];
    float p0 = pr[lane], p1 = pr[lane + 32];

    float n2 = p0 * p0 + p1 * p1;
    float sp = p0 + p1;
    float sx = x0 + x1;
    float px = p0 * x0 + p1 * x1;
#pragma unroll
    for (int o = 16; o; o >>= 1) {
        n2 += __shfl_xor_sync(0xffffffffu, n2, o);
        sp += __shfl_xor_sync(0xffffffffu, sp, o);
        sx += __shfl_xor_sync(0xffffffffu, sx, o);
        px += __shfl_xor_sync(0xffffffffu, px, o);
    }
    float inv = 1.0f / fmaxf(sqrtf(n2), EPSf);
    float u0 = p0 * inv, u1 = p1 * inv;
    float s = INV_SQRT_D * sp * inv;
    float p = INV_SQRT_D * sx;
    float q = px * inv;
    float dd = 1.0f + s + EPSf;
    float alpha = -p + (s * p - q) / dd;
    float beta  =  q - (p - s * q) / dd;
    float xc0 = x0 + alpha * u0 + beta * INV_SQRT_D;
    float xc1 = x1 + alpha * u1 + beta * INV_SQRT_D;

    __half* dst = &g_xh[row * 64];
    dst[lane] = __float2half(xc0);
    dst[lane + 32] = __float2half(xc1);
    float* d32 = &g_xc[row * 64];
    d32[lane] = xc0;
    d32[lane + 32] = xc1;
    if (lane == 0) g_ri[row] = make_float2(inv, s);
    gdc_launch();
}

// ---------------- kernel 2: fp16 HMMA distance screen + top-2 -------------
// grid 1024 = 128 Mtiles(64 rows) x 8 Ntiles(256 codes); 256 threads,
// 8 warps (2 in M x 4 in N), warp tile 32x64, 2 CTAs per SM. (R10 config)
#define ROWB 144
#define ASZ (64 * ROWB)
#define BSZ (256 * ROWB)
#define SMEMSZ (ASZ + BSZ + 256 * 4)

__global__ void __launch_bounds__(256, 2) argmin_kernel(void) {
    extern __shared__ char sm[];
    char* Asm = sm;
    char* Bsm = sm + ASZ;
    float* c2s = (float*)(sm + ASZ + BSZ);
    uint32_t* epi = (uint32_t*)Bsm;        // aliased onto B after mainloop

    const int tid = threadIdx.x;
    const int lane = tid & 31;
    const int wid = tid >> 5;
    const int wm = wid & 1;
    const int wn = wid >> 1;
    const int mb = blockIdx.x >> 3;
    const int nb = blockIdx.x & 7;

    const uint32_t smbA = smem_u32(Asm);
    const uint32_t smbB = smem_u32(Bsm);

    gdc_wait();   // wait for canon's g_xh/g_ch/g_c2 before consuming

    // stage A: 64 rows x 64 fp16
#pragma unroll 2
    for (int i = tid; i < 64 * 8; i += 256) {
        int r = i >> 3, f4 = i & 7;
        uint4 v = *reinterpret_cast<const uint4*>(
            &g_xh[(mb * 64 + r) * 64 + f4 * 8]);
        *reinterpret_cast<uint4*>(Asm + r * ROWB + f4 * 16) = v;
    }
    // stage B: 256 code rows x 64 fp16
#pragma unroll 4
    for (int i = tid; i < 256 * 8; i += 256) {
        int r = i >> 3, f4 = i & 7;
        uint4 v = *reinterpret_cast<const uint4*>(
            &g_ch[(nb * 256 + r) * 64 + f4 * 8]);
        *reinterpret_cast<uint4*>(Bsm + r * ROWB + f4 * 16) = v;
    }
    if (tid < 256) c2s[tid] = g_c2[nb * 256 + tid];
    __syncthreads();

    float acc[2][8][4];
#pragma unroll
    for (int i = 0; i < 2; i++)
#pragma unroll
        for (int j = 0; j < 8; j++)
#pragma unroll
            for (int kk = 0; kk < 4; kk++) acc[i][j][kk] = 0.0f;

#pragma unroll
    for (int ks = 0; ks < 4; ++ks) {
        const int kb = ks * 32;
        uint32_t a[2][4];
#pragma unroll
        for (int mi = 0; mi < 2; ++mi) {
            uint32_t addr = smbA + (wm * 32 + mi * 16 + (lane & 15)) * ROWB
                          + kb + ((lane >> 4) * 16);
            ldmx4(a[mi][0], a[mi][1], a[mi][2], a[mi][3], addr);
        }
        uint32_t b[8][2];
#pragma unroll
        for (int nj = 0; nj < 4; ++nj) {
            int nrow = wn * 64 + nj * 16 + (((lane >> 4) & 1) * 8) + (lane & 7);
            uint32_t addr = smbB + nrow * ROWB + kb + (((lane >> 3) & 1) * 16);
            ldmx4(b[nj * 2][0], b[nj * 2][1],
                  b[nj * 2 + 1][0], b[nj * 2 + 1][1], addr);
        }
#pragma unroll
        for (int mi = 0; mi < 2; ++mi)
#pragma unroll
            for (int nj = 0; nj < 8; ++nj)
                mma16816(acc[mi][nj], a[mi], b[nj]);
    }

    __syncthreads();   // done reading B; epi aliases B

    // warp-level top-2 per row over this warp's 64 cols
#pragma unroll
    for (int mi = 0; mi < 2; ++mi) {
#pragma unroll
        for (int h = 0; h < 2; ++h) {
            float d1 = INFINITY, d2 = INFINITY;
            int i1 = 0, i2 = 0;
#pragma unroll
            for (int nj = 0; nj < 8; ++nj) {
#pragma unroll
                for (int s = 0; s < 2; ++s) {
                    int cloc = wn * 64 + nj * 8 + 2 * (lane & 3) + s;
                    float d = fmaf(-2.0f, acc[mi][nj][h * 2 + s], c2s[cloc]);
                    int gi = nb * 256 + cloc;
                    if (d < d1) { d2 = d1; i2 = i1; d1 = d; i1 = gi; }
                    else if (d < d2) { d2 = d; i2 = gi; }
                }
            }
#pragma unroll
            for (int off = 1; off <= 2; off <<= 1) {
                float od1 = __shfl_xor_sync(0xffffffffu, d1, off);
                int   oi1 = __shfl_xor_sync(0xffffffffu, i1, off);
                float od2 = __shfl_xor_sync(0xffffffffu, d2, off);
                int   oi2 = __shfl_xor_sync(0xffffffffu, i2, off);
                if (d1 <= od1) {
                    if (od1 < d2) { d2 = od1; i2 = oi1; }
                } else {
                    if (d1 <= od2) { d2 = d1; i2 = i1; }
                    else           { d2 = od2; i2 = oi2; }
                    d1 = od1; i1 = oi1;
                }
            }
            if ((lane & 3) == 0) {
                int rowL = wm * 32 + mi * 16 + (lane >> 2) + h * 8;
                uint32_t* e = epi + (rowL * 4 + wn) * 4;
                e[0] = __float_as_uint(d1); e[1] = (uint32_t)i1;
                e[2] = __float_as_uint(d2); e[3] = (uint32_t)i2;
            }
        }
    }
    __syncthreads();

    // merge 4 n-warps -> block top-2 per row
    if (tid < 64) {
        float d1 = INFINITY, d2 = INFINITY;
        int i1 = 0, i2 = 0;
#pragma unroll
        for (int w = 0; w < 4; ++w) {
            const uint32_t* e = epi + (tid * 4 + w) * 4;
            float a1 = __uint_as_float(e[0]); int b1i = (int)e[1];
            float a2 = __uint_as_float(e[2]); int b2i = (int)e[3];
            if (a1 < d1) { d2 = d1; i2 = i1; d1 = a1; i1 = b1i; }
            else if (a1 < d2) { d2 = a1; i2 = b1i; }
            if (a2 < d1) { d2 = d1; i2 = i1; d1 = a2; i1 = b2i; }
            else if (a2 < d2) { d2 = a2; i2 = b2i; }
        }
        int rowG = mb * 64 + tid;
        g_cand[rowG * 8 + nb] =
            make_float4(d1, __int_as_float(i1), d2, __int_as_float(i2));
    }
    gdc_launch();
}

// ---------------- kernel 3: prune 16->4, exact rescore, rotate, loss ------
__global__ void final_kernel(const float* __restrict__ x,
                             const float* __restrict__ pq,
                             const float* __restrict__ codes,
                             float* __restrict__ out,
                             int has_idx, int has_loss) {
    __shared__ float bl;
    int tid = threadIdx.x;
    if (tid == 0) bl = 0.0f;
    __syncthreads();

    int row = blockIdx.x * 8 + (tid >> 5);
    int lane = tid & 31;

    gdc_wait();   // wait for argmin's g_cand (canon done transitively)

    // prune: top-4 by screened distance among 16 stored candidates
    float td[4] = {INFINITY, INFINITY, INFINITY, INFINITY};
    int   ti[4] = {0, 0, 0, 0};
#pragma unroll
    for (int nb = 0; nb < 8; ++nb) {
        float4 cd = g_cand[row * 8 + nb];
#pragma unroll
        for (int h = 0; h < 2; ++h) {
            float d = h ? cd.z : cd.x;
            int   ix = __float_as_int(h ? cd.w : cd.y);
#pragma unroll
            for (int k = 0; k < 4; ++k) {
                if (d < td[k] || (d == td[k] && ix < ti[k])) {
                    float pd = td[k]; int pi = ti[k];
                    td[k] = d; ti[k] = ix; d = pd; ix = pi;
                }
            }
        }
    }

    // load canon products instead of recomputing (chain 1 eliminated)
    float2 ri = g_ri[row];
    float inv = ri.x, s = ri.y;
    float dd = 1.0f + s + EPSf;
    const float* pr = pq + row * Dn;
    float p0 = pr[lane], p1 = pr[lane + 32];
    float u0 = p0 * inv, u1 = p1 * inv;
    float xc0 = g_xc[row * Dn + lane];
    float xc1 = g_xc[row * Dn + lane + 32];
    const float* xr = x + row * Dn;
    float x0 = xr[lane], x1 = xr[lane + 32];

    // chain A: exact fp32 rescore of the 4 pruned candidates
    float dk[4];
#pragma unroll
    for (int k = 0; k < 4; ++k) {
        const float* cr = codes + ti[k] * Dn;
        dk[k] = xc0 * cr[lane] + xc1 * cr[lane + 32];
    }
#pragma unroll
    for (int o = 16; o; o >>= 1) {
#pragma unroll
        for (int k = 0; k < 4; ++k)
            dk[k] += __shfl_xor_sync(0xffffffffu, dk[k], o);
    }
    int best = ti[0];
    float bd = g_c2[ti[0]] - 2.0f * dk[0];
#pragma unroll
    for (int k = 1; k < 4; ++k) {
        float d = g_c2[ti[k]] - 2.0f * dk[k];
        if (d < bd || (d == bd && ti[k] < best)) { bd = d; best = ti[k]; }
    }
    int idx = best;

    // chain B: winner's rotation sums + loss
    const float* qcr = codes + idx * Dn;
    float qc0 = qcr[lane], qc1 = qcr[lane + 32];

    float sq = qc0 + qc1;
    float pqv = u0 * qc0 + u1 * qc1;
    float l = (x0 - qc0) * (x0 - qc0) + (x1 - qc1) * (x1 - qc1);
#pragma unroll
    for (int o = 16; o; o >>= 1) {
        sq  += __shfl_xor_sync(0xffffffffu, sq, o);
        pqv += __shfl_xor_sync(0xffffffffu, pqv, o);
        l   += __shfl_xor_sync(0xffffffffu, l, o);
    }
    float pp = INV_SQRT_D * sq;
    float qq = pqv;
    float a = pp + (s * pp - qq) / dd;
    float b = -qq + (s * qq - pp) / dd;

    out[row * Dn + lane]      = qc0 + a * u0 + b * INV_SQRT_D;
    out[row * Dn + lane + 32] = qc1 + a * u1 + b * INV_SQRT_D;

    if (lane == 0) {
        if (has_idx) out[Bn * Dn + row] = (float)idx;
        atomicAdd(&bl, l);
    }
    __syncthreads();
    if (tid == 0) {
        atomicAdd(&g_loss, bl);
        __threadfence();
        unsigned int n = atomicAdd(&g_done, 1u);
        if (n == gridDim.x - 1) {
            if (has_loss) out[Bn * Dn + Bn] = g_loss * (1.25f / (float)Bn);
        }
    }
}

// ---------------- launcher ----------------
extern "C" void kernel_launch(void* const* d_in, const int* in_sizes, int n_in,
                              void* d_out, int out_size) {
    const float* x     = (const float*)d_in[0];
    const float* pq    = (const float*)d_in[1];
    const float* codes = (const float*)d_in[2];
    float* out = (float*)d_out;

    int has_idx  = out_size >= Bn * Dn + Bn;
    int has_loss = out_size >= Bn * Dn + Bn + 1;

    cudaFuncSetAttribute(argmin_kernel,
                         cudaFuncAttributeMaxDynamicSharedMemorySize, SMEMSZ);

    canon_kernel<<<Bn / 8 + Cn / 8, 256>>>(x, pq, codes);

    cudaLaunchAttribute attr[1];
    attr[0].id = cudaLaunchAttributeProgrammaticStreamSerialization;
    attr[0].val.programmaticStreamSerializationAllowed = 1;

    {
        cudaLaunchConfig_t cfg = {};
        cfg.gridDim = dim3((Bn / 64) * 8);
        cfg.blockDim = dim3(256);
        cfg.dynamicSmemBytes = SMEMSZ;
        cfg.stream = 0;
        cfg.attrs = attr;
        cfg.numAttrs = 1;
        cudaLaunchKernelEx(&cfg, argmin_kernel);
    }
    {
        cudaLaunchConfig_t cfg = {};
        cfg.gridDim = dim3(Bn / 8);
        cfg.blockDim = dim3(256);
        cfg.dynamicSmemBytes = 0;
        cfg.stream = 0;
        cfg.attrs = attr;
        cfg.numAttrs = 1;
        cudaLaunchKernelEx(&cfg, final_kernel, x, pq, codes, out,
                           has_idx, has_loss);
    }
}